// round 14
// baseline (speedup 1.0000x reference)
#include <cuda_runtime.h>
#include <cuda_fp16.h>

#define N_NODES 50000
#define N_FEAT  128
#define N_EDGES 600000
#define N_POWERS 3

// fp16 staging copy of x (halves gather traffic + L1 wavefronts).
__device__ __half g_x16[(size_t)N_NODES * N_FEAT];

// 1 if edge_index is genuinely int64 on device, 0 if int32 (JAX x64-off).
__device__ int g_idx_is64;

__global__ void __launch_bounds__(256)
convert_x_kernel(const float* __restrict__ x, const int* __restrict__ ei32)
{
    if (blockIdx.x == 0 && threadIdx.x == 0) {
        int all_zero = 1;
#pragma unroll
        for (int k = 1; k < 256; k += 2) all_zero &= (ei32[k] == 0);
        g_idx_is64 = all_zero;
    }
    const int i = (blockIdx.x * blockDim.x + threadIdx.x) * 4;
    if (i < N_NODES * N_FEAT) {
        const float4 v = *reinterpret_cast<const float4*>(x + i);
        __half2 h0 = __floats2half2_rn(v.x, v.y);
        __half2 h1 = __floats2half2_rn(v.z, v.w);
        uint2 packed;
        packed.x = *reinterpret_cast<unsigned*>(&h0);
        packed.y = *reinterpret_cast<unsigned*>(&h1);
        *reinterpret_cast<uint2*>(&g_x16[i]) = packed;
    }
}

// abs via sign-mask (LOP3 on alu pipe instead of HABS2 on fma pipe).
static __device__ __forceinline__ __half2 habs2_and(__half2 v) {
    unsigned u = *reinterpret_cast<unsigned*>(&v) & 0x7FFF7FFFu;
    return *reinterpret_cast<__half2*>(&u);
}

// Fold half2 -> float (sum of both halves).
static __device__ __forceinline__ float hfold(__half2 a) {
    return __low2float(__hadd2(a, __lowhigh2highlow(a)));
}

// Fold two half2 accumulators into one packed half2 (lane-local sums).
static __device__ __forceinline__ __half2 hfold_pack(__half2 a, __half2 b) {
    const __half2 sa = __hadd2(a, __lowhigh2highlow(a));
    const __half2 sb = __hadd2(b, __lowhigh2highlow(b));
    return __halves2half2(__low2half(sa), __low2half(sb));
}

static __device__ __forceinline__ __half2 shfl_xor_h2(__half2 v, int off) {
    unsigned u = *reinterpret_cast<unsigned*>(&v);
    u = __shfl_xor_sync(0xFFFFFFFFu, u, off);
    return *reinterpret_cast<__half2*>(&u);
}

// In-loop shared load of 4 half2 weights; volatile so ptxas cannot hoist the
// weights into loop-carried registers (the point is freeing those regs).
static __device__ __forceinline__ void lds_w4(__half2 w[4], unsigned addr) {
    uint4 v;
    asm volatile("ld.shared.v4.u32 {%0,%1,%2,%3}, [%4];"
                 : "=r"(v.x), "=r"(v.y), "=r"(v.z), "=r"(v.w) : "r"(addr));
    *reinterpret_cast<uint4*>(w) = v;
}

// Weight smem layout: lane l (0..7) x h (0..2) x chunk (0..1) x 4 half2.
// Byte addr = l*112 + h*32 + chunk*16 (112 stride -> conflict-free LDS.128).
#define WS_BYTES (8 * 112)

// 8 lanes per edge, 8 edges per warp-iteration (group g handles edges
// 2g, 2g+1 = streams A, B). Lane l owns features [8l,8l+8) (chunk 0) and
// [64+8l,+8) (chunk 1); each warp LDG.128 covers exactly one 128B line per
// edge-row. Two-phase register reuse (16 data regs) + weights in SMEM
// (reloaded in-loop) squeezes regs to ~50 -> 5 CTAs/SM (40 warps) for
// latency hiding. Packed (h0,h1) half2 reduction, direct store.
__global__ void __launch_bounds__(256, 5)
adj_learn_kernel(const void* __restrict__ edge_index_raw,
                 const float* __restrict__ Wa,
                 const float* __restrict__ ba,
                 const float* __restrict__ Wb,
                 const float* __restrict__ bb,
                 float* __restrict__ out)
{
    __shared__ __align__(16) unsigned char ws[WS_BYTES];

    const int p    = blockIdx.y;
    const int tid  = threadIdx.x;
    const int lane = tid & 31;
    const int l    = lane & 7;        // lane within edge-group
    const int g    = lane >> 3;       // edge-pair slot 0..3
    const int warp = tid >> 5;
    const int warps_per_block = blockDim.x >> 5;
    const int gwarp  = blockIdx.x * warps_per_block + warp;
    const int nwarps = gridDim.x * warps_per_block;

    // Fill weight smem: 192 half2 values, one per thread t<192.
    const float* Wap = Wa + (size_t)p * (N_FEAT * 3);
    if (tid < 192) {
        const int wl = tid / 24;          // 0..7
        const int wh = (tid / 8) % 3;     // 0..2
        const int wk = tid % 8;           // 0..7
        const int feat0 = (wk < 4) ? (8 * wl + 2 * wk) : (64 + 8 * wl + 2 * (wk - 4));
        const __half2 v = __floats2half2_rn(Wap[feat0 * 3 + wh],
                                            Wap[(feat0 + 1) * 3 + wh]);
        *reinterpret_cast<__half2*>(&ws[wl * 112 + wh * 32 + (wk / 4) * 16 + (wk % 4) * 4]) = v;
    }
    __syncthreads();

    unsigned ws_base;
    {
        unsigned ptr = (unsigned)__cvta_generic_to_shared(ws);
        ws_base = ptr + (unsigned)(l * 112);
    }

    const int shift = g_idx_is64;     // 0: int32 words, 1: int64 (read low word)

    const float ba0 = ba[p * 3 + 0];
    const float ba1 = ba[p * 3 + 1];
    const float ba2 = ba[p * 3 + 2];
    const float wb0 = Wb[p * 3 + 0];
    const float wb1 = Wb[p * 3 + 1];
    const float wb2 = Wb[p * 3 + 2];
    const float bbv = bb[p];

    const int* ei32 = (const int*)edge_index_raw;
    const int  src_base = p * 2 * N_EDGES;        // element index
    const int  dst_base = src_base + N_EDGES;
    float* outp = out + (size_t)p * N_EDGES;

    const int fA = l * 8;
    const int fB = 64 + l * 8;

    const int n_sup = N_EDGES / 8;    // 75000 super-groups of 8 edges

    for (int si = gwarp; si < n_sup; si += nwarps) {
        const int e = si * 8 + 2 * g;
        const int sA = ei32[(size_t)(src_base + e)     << shift];
        const int sB = ei32[(size_t)(src_base + e + 1) << shift];
        const int dA = ei32[(size_t)(dst_base + e)     << shift];
        const int dB = ei32[(size_t)(dst_base + e + 1) << shift];

        const __half* rjA = &g_x16[(size_t)sA * N_FEAT];
        const __half* riA = &g_x16[(size_t)dA * N_FEAT];
        const __half* rjB = &g_x16[(size_t)sB * N_FEAT];
        const __half* riB = &g_x16[(size_t)dB * N_FEAT];

        __half2 a0A = __float2half2_rn(0.f), a1A = a0A, a2A = a0A;
        __half2 a0B = a0A, a1B = a0A, a2B = a0A;

        // ---- Phase 1: chunk-0 of all 4 rows (16 data regs) ----
        {
            __half2 jvA[4], ivA[4], jvB[4], ivB[4];
            *reinterpret_cast<uint4*>(jvA) = *reinterpret_cast<const uint4*>(rjA + fA);
            *reinterpret_cast<uint4*>(ivA) = *reinterpret_cast<const uint4*>(riA + fA);
            *reinterpret_cast<uint4*>(jvB) = *reinterpret_cast<const uint4*>(rjB + fA);
            *reinterpret_cast<uint4*>(ivB) = *reinterpret_cast<const uint4*>(riB + fA);

            __half2 w0[4], w1[4], w2c[4];
            lds_w4(w0,  ws_base +  0);
            lds_w4(w1,  ws_base + 32);
            lds_w4(w2c, ws_base + 64);
#pragma unroll
            for (int k = 0; k < 4; ++k) {
                const __half2 dhA = habs2_and(__hsub2(jvA[k], ivA[k]));
                const __half2 dhB = habs2_and(__hsub2(jvB[k], ivB[k]));
                a0A = __hfma2(dhA, w0[k],  a0A);
                a0B = __hfma2(dhB, w0[k],  a0B);
                a1A = __hfma2(dhA, w1[k],  a1A);
                a1B = __hfma2(dhB, w1[k],  a1B);
                a2A = __hfma2(dhA, w2c[k], a2A);
                a2B = __hfma2(dhB, w2c[k], a2B);
            }
        }
        // ---- Phase 2: chunk-1 (same registers reused) ----
        {
            __half2 jvA[4], ivA[4], jvB[4], ivB[4];
            *reinterpret_cast<uint4*>(jvA) = *reinterpret_cast<const uint4*>(rjA + fB);
            *reinterpret_cast<uint4*>(ivA) = *reinterpret_cast<const uint4*>(riA + fB);
            *reinterpret_cast<uint4*>(jvB) = *reinterpret_cast<const uint4*>(rjB + fB);
            *reinterpret_cast<uint4*>(ivB) = *reinterpret_cast<const uint4*>(riB + fB);

            __half2 w0[4], w1[4], w2c[4];
            lds_w4(w0,  ws_base + 16);
            lds_w4(w1,  ws_base + 48);
            lds_w4(w2c, ws_base + 80);
#pragma unroll
            for (int k = 0; k < 4; ++k) {
                const __half2 dhA = habs2_and(__hsub2(jvA[k], ivA[k]));
                const __half2 dhB = habs2_and(__hsub2(jvB[k], ivB[k]));
                a0A = __hfma2(dhA, w0[k],  a0A);
                a0B = __hfma2(dhB, w0[k],  a0B);
                a1A = __hfma2(dhA, w1[k],  a1A);
                a1B = __hfma2(dhB, w1[k],  a1B);
                a2A = __hfma2(dhA, w2c[k], a2A);
                a2B = __hfma2(dhB, w2c[k], a2B);
            }
        }

        // Fold: (h0,h1) packed as half2, h2 as fp32, per stream.
        const __half2 pkA = hfold_pack(a0A, a1A);
        const __half2 pkB = hfold_pack(a0B, a1B);
        const float   x2A = hfold(a2A);
        const float   x2B = hfold(a2B);

        // Parity-interleaved butterfly over the 8-lane group.
        const bool oddl = (lane & 1);
        __half2 pk_keep = oddl ? pkB : pkA;
        __half2 pk_send = oddl ? pkA : pkB;
        float   x2_keep = oddl ? x2B : x2A;
        float   x2_send = oddl ? x2A : x2B;

        __half2 pk = __hadd2(pk_keep, shfl_xor_h2(pk_send, 1));
        float   x2 = x2_keep + __shfl_xor_sync(0xFFFFFFFFu, x2_send, 1);
#pragma unroll
        for (int off = 2; off <= 4; off <<= 1) {
            pk = __hadd2(pk, shfl_xor_h2(pk, off));
            x2 += __shfl_xor_sync(0xFFFFFFFFu, x2, off);
        }
        // Lane 8g holds edge 2g's (h0,h1,h2); lane 8g+1 holds edge 2g+1's.

        const float y0 = __low2float(pk);
        const float y1 = __high2float(pk);
        const float h0 = fmaxf(y0 + ba0, 0.f);
        const float h1 = fmaxf(y1 + ba1, 0.f);
        const float h2 = fmaxf(x2 + ba2, 0.f);
        const float z  = h0 * wb0 + h1 * wb1 + h2 * wb2 + bbv;
        const float r  = __fdividef(1.0f, 1.0f + __expf(-z));
        // Lanes {8g, 8g+1} store edges {2g, 2g+1}: one 32B coalesced store.
        if (l < 2) outp[si * 8 + 2 * g + (lane & 1)] = r;
    }
}

extern "C" void kernel_launch(void* const* d_in, const int* in_sizes, int n_in,
                              void* d_out, int out_size)
{
    const float* x  = (const float*)d_in[0];
    const void*  ei = d_in[1];
    const float* Wa = (const float*)d_in[2];
    const float* ba = (const float*)d_in[3];
    const float* Wb = (const float*)d_in[4];
    const float* bb = (const float*)d_in[5];
    float* out = (float*)d_out;

    convert_x_kernel<<<(N_NODES * N_FEAT / 4 + 255) / 256, 256>>>(x, (const int*)ei);

    // 741 CTAs ~= one wave at 5 CTAs/SM x 148 SMs.
    dim3 grid(247, N_POWERS, 1);
    dim3 block(256, 1, 1);
    adj_learn_kernel<<<grid, block>>>(ei, Wa, ba, Wb, bb, out);
}

// round 15
// speedup vs baseline: 1.0279x; 1.0279x over previous
#include <cuda_runtime.h>
#include <cuda_fp16.h>

#define N_NODES 50000
#define N_FEAT  128
#define N_EDGES 600000
#define N_POWERS 3

// fp16 staging copy of x (halves gather traffic + L1 wavefronts).
__device__ __half g_x16[(size_t)N_NODES * N_FEAT];

// 1 if edge_index is genuinely int64 on device, 0 if int32 (JAX x64-off).
__device__ int g_idx_is64;

__global__ void __launch_bounds__(256)
convert_x_kernel(const float* __restrict__ x, const int* __restrict__ ei32)
{
    if (blockIdx.x == 0 && threadIdx.x == 0) {
        int all_zero = 1;
#pragma unroll
        for (int k = 1; k < 256; k += 2) all_zero &= (ei32[k] == 0);
        g_idx_is64 = all_zero;
    }
    const int i = (blockIdx.x * blockDim.x + threadIdx.x) * 4;
    if (i < N_NODES * N_FEAT) {
        const float4 v = *reinterpret_cast<const float4*>(x + i);
        __half2 h0 = __floats2half2_rn(v.x, v.y);
        __half2 h1 = __floats2half2_rn(v.z, v.w);
        uint2 packed;
        packed.x = *reinterpret_cast<unsigned*>(&h0);
        packed.y = *reinterpret_cast<unsigned*>(&h1);
        *reinterpret_cast<uint2*>(&g_x16[i]) = packed;
    }
}

// abs via sign-mask (LOP3 on alu pipe instead of HABS2 on fma pipe).
static __device__ __forceinline__ __half2 habs2_and(__half2 v) {
    unsigned u = *reinterpret_cast<unsigned*>(&v) & 0x7FFF7FFFu;
    return *reinterpret_cast<__half2*>(&u);
}

// Fold half2 -> float (sum of both halves).
static __device__ __forceinline__ float hfold(__half2 a) {
    return __low2float(__hadd2(a, __lowhigh2highlow(a)));
}

// Fold two half2 accumulators into one packed half2 (lane-local sums).
static __device__ __forceinline__ __half2 hfold_pack(__half2 a, __half2 b) {
    const __half2 sa = __hadd2(a, __lowhigh2highlow(a));
    const __half2 sb = __hadd2(b, __lowhigh2highlow(b));
    return __halves2half2(__low2half(sa), __low2half(sb));
}

static __device__ __forceinline__ __half2 shfl_xor_h2(__half2 v, int off) {
    unsigned u = *reinterpret_cast<unsigned*>(&v);
    u = __shfl_xor_sync(0xFFFFFFFFu, u, off);
    return *reinterpret_cast<__half2*>(&u);
}

// Broadcast load of 4 floats from smem (all lanes same address -> 1 wavefront).
static __device__ __forceinline__ float4 lds_f4(unsigned addr) {
    float4 v;
    asm volatile("ld.shared.v4.f32 {%0,%1,%2,%3}, [%4];"
                 : "=f"(v.x), "=f"(v.y), "=f"(v.z), "=f"(v.w) : "r"(addr));
    return v;
}

// 8 lanes per edge, 8 edges per warp-iteration (group g handles edges
// 2g, 2g+1 = streams A, B). Lane l owns features [8l,8l+8) (chunk 0) and
// [64+8l,+8) (chunk 1); each warp LDG.128 covers exactly one 128B line per
// edge-row. Two-phase register reuse (16 data regs). Next iteration's 4
// indices are register-prefetched, halving the per-iteration serial memory
// chain. The 7 epilogue scalars live in smem (2 broadcast LDS.128/iter)
// to keep regs <= 64 -> 4 CTAs/SM.
__global__ void __launch_bounds__(256, 4)
adj_learn_kernel(const void* __restrict__ edge_index_raw,
                 const float* __restrict__ Wa,
                 const float* __restrict__ ba,
                 const float* __restrict__ Wb,
                 const float* __restrict__ bb,
                 float* __restrict__ out)
{
    __shared__ __align__(16) float ec[8];   // ba0,ba1,ba2,wb0 | wb1,wb2,bbv,0

    const int p    = blockIdx.y;
    const int tid  = threadIdx.x;
    const int lane = tid & 31;
    const int l    = lane & 7;        // lane within edge-group
    const int g    = lane >> 3;       // edge-pair slot 0..3
    const int warp = tid >> 5;
    const int warps_per_block = blockDim.x >> 5;
    const int gwarp  = blockIdx.x * warps_per_block + warp;
    const int nwarps = gridDim.x * warps_per_block;

    if (tid == 0) {
        ec[0] = ba[p * 3 + 0];
        ec[1] = ba[p * 3 + 1];
        ec[2] = ba[p * 3 + 2];
        ec[3] = Wb[p * 3 + 0];
        ec[4] = Wb[p * 3 + 1];
        ec[5] = Wb[p * 3 + 2];
        ec[6] = bb[p];
        ec[7] = 0.f;
    }

    const int fA = l * 8;
    const int fB = 64 + l * 8;

    // Per-lane weights: half2 feature-pairs, k=0..3 -> chunk fA, k=4..7 -> fB.
    const float* Wap = Wa + (size_t)p * (N_FEAT * 3);
    __half2 w2[3][8];
#pragma unroll
    for (int k = 0; k < 4; ++k) {
#pragma unroll
        for (int h = 0; h < 3; ++h) {
            w2[h][k]     = __floats2half2_rn(Wap[(fA + 2 * k) * 3 + h],
                                             Wap[(fA + 2 * k + 1) * 3 + h]);
            w2[h][k + 4] = __floats2half2_rn(Wap[(fB + 2 * k) * 3 + h],
                                             Wap[(fB + 2 * k + 1) * 3 + h]);
        }
    }
    __syncthreads();

    const unsigned ec_addr = (unsigned)__cvta_generic_to_shared(ec);
    const int shift = g_idx_is64;     // 0: int32 words, 1: int64 (read low word)

    const int* ei32 = (const int*)edge_index_raw;
    const int  src_base = p * 2 * N_EDGES;        // element index
    const int  dst_base = src_base + N_EDGES;
    float* outp = out + (size_t)p * N_EDGES;

    const int n_sup = N_EDGES / 8;    // 75000 super-groups of 8 edges

    if (gwarp >= n_sup) return;

    // First iteration's indices.
    int sA, sB, dA, dB;
    {
        const int e = gwarp * 8 + 2 * g;
        sA = ei32[(size_t)(src_base + e)     << shift];
        sB = ei32[(size_t)(src_base + e + 1) << shift];
        dA = ei32[(size_t)(dst_base + e)     << shift];
        dB = ei32[(size_t)(dst_base + e + 1) << shift];
    }

    for (int si = gwarp; si < n_sup; si += nwarps) {
        // Register-prefetch next iteration's indices (clamped in-bounds).
        const int snx = (si + nwarps < n_sup) ? (si + nwarps) : si;
        int sAn, sBn, dAn, dBn;
        {
            const int en = snx * 8 + 2 * g;
            sAn = ei32[(size_t)(src_base + en)     << shift];
            sBn = ei32[(size_t)(src_base + en + 1) << shift];
            dAn = ei32[(size_t)(dst_base + en)     << shift];
            dBn = ei32[(size_t)(dst_base + en + 1) << shift];
        }

        const __half* rjA = &g_x16[(size_t)sA * N_FEAT];
        const __half* riA = &g_x16[(size_t)dA * N_FEAT];
        const __half* rjB = &g_x16[(size_t)sB * N_FEAT];
        const __half* riB = &g_x16[(size_t)dB * N_FEAT];

        __half2 a0A = __float2half2_rn(0.f), a1A = a0A, a2A = a0A;
        __half2 a0B = a0A, a1B = a0A, a2B = a0A;

        // ---- Phase 1: chunk-0 of all 4 rows (16 data regs) ----
        {
            __half2 jvA[4], ivA[4], jvB[4], ivB[4];
            *reinterpret_cast<uint4*>(jvA) = *reinterpret_cast<const uint4*>(rjA + fA);
            *reinterpret_cast<uint4*>(ivA) = *reinterpret_cast<const uint4*>(riA + fA);
            *reinterpret_cast<uint4*>(jvB) = *reinterpret_cast<const uint4*>(rjB + fA);
            *reinterpret_cast<uint4*>(ivB) = *reinterpret_cast<const uint4*>(riB + fA);
#pragma unroll
            for (int k = 0; k < 4; ++k) {
                const __half2 dhA = habs2_and(__hsub2(jvA[k], ivA[k]));
                const __half2 dhB = habs2_and(__hsub2(jvB[k], ivB[k]));
                a0A = __hfma2(dhA, w2[0][k], a0A);
                a0B = __hfma2(dhB, w2[0][k], a0B);
                a1A = __hfma2(dhA, w2[1][k], a1A);
                a1B = __hfma2(dhB, w2[1][k], a1B);
                a2A = __hfma2(dhA, w2[2][k], a2A);
                a2B = __hfma2(dhB, w2[2][k], a2B);
            }
        }
        // ---- Phase 2: chunk-1 (same registers reused) ----
        {
            __half2 jvA[4], ivA[4], jvB[4], ivB[4];
            *reinterpret_cast<uint4*>(jvA) = *reinterpret_cast<const uint4*>(rjA + fB);
            *reinterpret_cast<uint4*>(ivA) = *reinterpret_cast<const uint4*>(riA + fB);
            *reinterpret_cast<uint4*>(jvB) = *reinterpret_cast<const uint4*>(rjB + fB);
            *reinterpret_cast<uint4*>(ivB) = *reinterpret_cast<const uint4*>(riB + fB);
#pragma unroll
            for (int k = 0; k < 4; ++k) {
                const __half2 dhA = habs2_and(__hsub2(jvA[k], ivA[k]));
                const __half2 dhB = habs2_and(__hsub2(jvB[k], ivB[k]));
                a0A = __hfma2(dhA, w2[0][k + 4], a0A);
                a0B = __hfma2(dhB, w2[0][k + 4], a0B);
                a1A = __hfma2(dhA, w2[1][k + 4], a1A);
                a1B = __hfma2(dhB, w2[1][k + 4], a1B);
                a2A = __hfma2(dhA, w2[2][k + 4], a2A);
                a2B = __hfma2(dhB, w2[2][k + 4], a2B);
            }
        }

        // Fold: (h0,h1) packed as half2, h2 as fp32, per stream.
        const __half2 pkA = hfold_pack(a0A, a1A);
        const __half2 pkB = hfold_pack(a0B, a1B);
        const float   x2A = hfold(a2A);
        const float   x2B = hfold(a2B);

        // Parity-interleaved butterfly over the 8-lane group.
        const bool oddl = (lane & 1);
        __half2 pk_keep = oddl ? pkB : pkA;
        __half2 pk_send = oddl ? pkA : pkB;
        float   x2_keep = oddl ? x2B : x2A;
        float   x2_send = oddl ? x2A : x2B;

        __half2 pk = __hadd2(pk_keep, shfl_xor_h2(pk_send, 1));
        float   x2 = x2_keep + __shfl_xor_sync(0xFFFFFFFFu, x2_send, 1);
#pragma unroll
        for (int off = 2; off <= 4; off <<= 1) {
            pk = __hadd2(pk, shfl_xor_h2(pk, off));
            x2 += __shfl_xor_sync(0xFFFFFFFFu, x2, off);
        }
        // Lane 8g holds edge 2g's (h0,h1,h2); lane 8g+1 holds edge 2g+1's.

        // Epilogue constants from smem (broadcast, 2 wavefronts).
        const float4 c0 = lds_f4(ec_addr);        // ba0,ba1,ba2,wb0
        const float4 c1 = lds_f4(ec_addr + 16);   // wb1,wb2,bbv,0

        const float y0 = __low2float(pk);
        const float y1 = __high2float(pk);
        const float h0 = fmaxf(y0 + c0.x, 0.f);
        const float h1 = fmaxf(y1 + c0.y, 0.f);
        const float h2 = fmaxf(x2 + c0.z, 0.f);
        const float z  = h0 * c0.w + h1 * c1.x + h2 * c1.y + c1.z;
        const float r  = __fdividef(1.0f, 1.0f + __expf(-z));
        // Lanes {8g, 8g+1} store edges {2g, 2g+1}: one 32B coalesced store.
        if (l < 2) outp[si * 8 + 2 * g + (lane & 1)] = r;

        sA = sAn; sB = sBn; dA = dAn; dB = dBn;
    }
}

extern "C" void kernel_launch(void* const* d_in, const int* in_sizes, int n_in,
                              void* d_out, int out_size)
{
    const float* x  = (const float*)d_in[0];
    const void*  ei = d_in[1];
    const float* Wa = (const float*)d_in[2];
    const float* ba = (const float*)d_in[3];
    const float* Wb = (const float*)d_in[4];
    const float* bb = (const float*)d_in[5];
    float* out = (float*)d_out;

    convert_x_kernel<<<(N_NODES * N_FEAT / 4 + 255) / 256, 256>>>(x, (const int*)ei);

    // 591 CTAs ~= one wave at 4 CTAs/SM x 148 SMs.
    dim3 grid(197, N_POWERS, 1);
    dim3 block(256, 1, 1);
    adj_learn_kernel<<<grid, block>>>(ei, Wa, ba, Wb, bb, out);
}